// round 16
// baseline (speedup 1.0000x reference)
#include <cuda_runtime.h>
#include <math.h>

// Scratch (no cudaMalloc allowed)
__device__ float g_feats[32 * 1280];   // [B, (K+1)*C] pooled means
__device__ float g_h[32 * 32];         // [MID][B] hidden after BN+ReLU (transposed)
__device__ float g_w1[32 * 256];       // [B, C] sigmoid self-gate
__device__ float g_w2[32 * 4 * 256];   // [B, K, C] softmax branch gates

#define B_ 32
#define C_ 256
#define K_ 4
#define HW_ 1024
#define MID_ 32
#define FEAT_ 1280   // (K+1)*C

// ---------------- Kernel 1: global average pool (R9-proven best) ----------------
__global__ void k_means(const float* __restrict__ y,
                        const float* __restrict__ x0,
                        const float* __restrict__ x1,
                        const float* __restrict__ x2,
                        const float* __restrict__ x3) {
    int warp = (blockIdx.x * blockDim.x + threadIdx.x) >> 5;
    int lane = threadIdx.x & 31;
    int b = warp / FEAT_;
    int j = warp - b * FEAT_;       // slot*256 + c
    int slot = j >> 8;
    int c = j & 255;
    const float* base;
    switch (slot) {
        case 0: base = y;  break;
        case 1: base = x0; break;
        case 2: base = x1; break;
        case 3: base = x2; break;
        default: base = x3; break;
    }
    const float4* p = reinterpret_cast<const float4*>(base + (size_t)(b * C_ + c) * HW_);
    float s = 0.f;
#pragma unroll
    for (int i = 0; i < 8; i++) {
        float4 v = p[lane + i * 32];
        s += (v.x + v.y) + (v.z + v.w);
    }
#pragma unroll
    for (int o = 16; o; o >>= 1) s += __shfl_xor_sync(0xffffffffu, s, o);
    if (lane == 0) g_feats[warp] = s * (1.0f / 1024.0f);
}

// ---------------- Kernel 2a: GEMM1 + BN + ReLU, weight-coalesced (R9-proven) -------
__global__ void k_gate1(const float* __restrict__ conv1_w,   // [32,1280]
                        const float* __restrict__ bn_gamma,
                        const float* __restrict__ bn_beta,
                        const float* __restrict__ bn_mean,
                        const float* __restrict__ bn_var) {
    cudaTriggerProgrammaticLaunchCompletion();

    int m = blockIdx.x;
    int t = threadIdx.x;
    __shared__ float sw[FEAT_];

    for (int i = t; i < FEAT_; i += 256) sw[i] = conv1_w[m * FEAT_ + i];
    float mean = bn_mean[m];
    float scale = bn_gamma[m] * rsqrtf(bn_var[m] + 1e-5f);
    float beta = bn_beta[m];

    cudaGridDependencySynchronize();
    __syncthreads();

    int w = t >> 5, lane = t & 31;
#pragma unroll
    for (int bb = 0; bb < 4; bb++) {
        int b = w * 4 + bb;
        const float* f = g_feats + b * FEAT_;
        float s = 0.f;
#pragma unroll
        for (int k = 0; k < FEAT_ / 32; k++)
            s = fmaf(f[lane + k * 32], sw[lane + k * 32], s);
#pragma unroll
        for (int o = 16; o; o >>= 1) s += __shfl_xor_sync(0xffffffffu, s, o);
        if (lane == 0)
            g_h[m * B_ + b] = fmaxf(fmaf(s - mean, scale, beta), 0.f);
    }
}

// ---------------- Kernel 2b: GEMM2 + activations, weight-coalesced (R9-proven) -----
__global__ void k_gate2(const float* __restrict__ conv2_w,   // [1280,32]
                        const float* __restrict__ conv2_b) { // [1280]
    cudaTriggerProgrammaticLaunchCompletion();

    int cg = blockIdx.x;        // channels [cg*8, cg*8+8)
    int t = threadIdx.x;        // 256
    int c_local = t & 7;
    int b = t >> 3;

    __shared__ float sh2[5 * 8 * 33];            // [slot][c_local][mid], padded
    __shared__ float shh[MID_ * B_];             // [mid][b]

#pragma unroll
    for (int slot = 0; slot < 5; slot++) {
        int row = t >> 5, mid = t & 31;
        sh2[(slot * 8 + row) * 33 + mid] = conv2_w[(slot * 256 + cg * 8) * 32 + t];
    }
    float bias[5];
#pragma unroll
    for (int slot = 0; slot < 5; slot++)
        bias[slot] = conv2_b[slot * 256 + cg * 8 + c_local];

    cudaGridDependencySynchronize();
    for (int i = t; i < MID_ * B_; i += 256) shh[i] = g_h[i];
    __syncthreads();

    int c = cg * 8 + c_local;
    float v[5];
#pragma unroll
    for (int slot = 0; slot < 5; slot++) {
        float s = bias[slot];
        const float* wp = &sh2[(slot * 8 + c_local) * 33];
#pragma unroll
        for (int mid = 0; mid < MID_; mid++)
            s = fmaf(shh[mid * B_ + b], wp[mid], s);
        v[slot] = s;
    }

    g_w1[b * C_ + c] = 1.0f / (1.0f + expf(-v[0]));
    float mx = fmaxf(fmaxf(v[1], v[2]), fmaxf(v[3], v[4]));
    float e1 = expf(v[1] - mx), e2 = expf(v[2] - mx);
    float e3 = expf(v[3] - mx), e4 = expf(v[4] - mx);
    float inv = 1.0f / (e1 + e2 + e3 + e4);
    int gb = b * K_ * C_ + c;
    g_w2[gb + 0 * C_] = e1 * inv;
    g_w2[gb + 1 * C_] = e2 * inv;
    g_w2[gb + 2 * C_] = e3 * inv;
    g_w2[gb + 3 * C_] = e4 * inv;
}

// ---------------- Kernel 3: apply gates (4 sweeps/thread, reversed, PDL) -----------
// Block covers 4 (b,c) rows (1024 float4). Sweeps 0-1 prefetched before the
// dependency sync (overlap with gates); sweeps 2-3 stream after, pipelined
// against sweep 0-1's FMA+STG.
__global__ void k_apply(const float* __restrict__ y,
                        const float* __restrict__ x0,
                        const float* __restrict__ x1,
                        const float* __restrict__ x2,
                        const float* __restrict__ x3,
                        float* __restrict__ out) {
    int blk = gridDim.x - 1 - blockIdx.x;            // reversed
    int t = threadIdx.x;
    int i0 = blk * 1024 + t;                         // sweep 0 (row 4*blk+0)
    int i1 = i0 + 256;                               // sweep 1 (row 4*blk+1)
    int i2 = i0 + 512;                               // sweep 2 (row 4*blk+2)
    int i3 = i0 + 768;                               // sweep 3 (row 4*blk+3)

    const float4* Y  = reinterpret_cast<const float4*>(y);
    const float4* X0 = reinterpret_cast<const float4*>(x0);
    const float4* X1 = reinterpret_cast<const float4*>(x1);
    const float4* X2 = reinterpret_cast<const float4*>(x2);
    const float4* X3 = reinterpret_cast<const float4*>(x3);

    // Prefetch sweeps 0-1 before the sync (overlaps gate kernels via PDL)
    float4 ya = Y[i0],  yb = Y[i1];
    float4 p0 = X0[i0], q0 = X0[i1];
    float4 p1 = X1[i0], q1 = X1[i1];
    float4 p2 = X2[i0], q2 = X2[i1];
    float4 p3 = X3[i0], q3 = X3[i1];

    cudaGridDependencySynchronize();

    int bc0 = blk * 4;                               // rows bc0..bc0+3
    int b = bc0 >> 8;                                // all 4 rows in same batch (256|4)
    int cb = bc0 & 255;
    int gbase = b * K_ * C_;

    float w1a = g_w1[bc0],     w1b = g_w1[bc0 + 1];
    float a0 = g_w2[gbase + 0 * C_ + cb],     b0 = g_w2[gbase + 0 * C_ + cb + 1];
    float a1 = g_w2[gbase + 1 * C_ + cb],     b1 = g_w2[gbase + 1 * C_ + cb + 1];
    float a2 = g_w2[gbase + 2 * C_ + cb],     b2 = g_w2[gbase + 2 * C_ + cb + 1];
    float a3 = g_w2[gbase + 3 * C_ + cb],     b3 = g_w2[gbase + 3 * C_ + cb + 1];

    // Issue sweep 2-3 loads now: they pipeline against sweep 0-1 compute/stores
    float4 yc = Y[i2],  yd = Y[i3];
    float4 r0 = X0[i2], s0 = X0[i3];
    float4 r1 = X1[i2], s1 = X1[i3];
    float4 r2 = X2[i2], s2 = X2[i3];
    float4 r3 = X3[i2], s3 = X3[i3];

    float4 o0;
    o0.x = fmaf(ya.x, w1a, fmaf(a0, p0.x, fmaf(a1, p1.x, fmaf(a2, p2.x, a3 * p3.x))));
    o0.y = fmaf(ya.y, w1a, fmaf(a0, p0.y, fmaf(a1, p1.y, fmaf(a2, p2.y, a3 * p3.y))));
    o0.z = fmaf(ya.z, w1a, fmaf(a0, p0.z, fmaf(a1, p1.z, fmaf(a2, p2.z, a3 * p3.z))));
    o0.w = fmaf(ya.w, w1a, fmaf(a0, p0.w, fmaf(a1, p1.w, fmaf(a2, p2.w, a3 * p3.w))));
    __stcs(reinterpret_cast<float4*>(out) + i0, o0);

    float4 o1;
    o1.x = fmaf(yb.x, w1b, fmaf(b0, q0.x, fmaf(b1, q1.x, fmaf(b2, q2.x, b3 * q3.x))));
    o1.y = fmaf(yb.y, w1b, fmaf(b0, q0.y, fmaf(b1, q1.y, fmaf(b2, q2.y, b3 * q3.y))));
    o1.z = fmaf(yb.z, w1b, fmaf(b0, q0.z, fmaf(b1, q1.z, fmaf(b2, q2.z, b3 * q3.z))));
    o1.w = fmaf(yb.w, w1b, fmaf(b0, q0.w, fmaf(b1, q1.w, fmaf(b2, q2.w, b3 * q3.w))));
    __stcs(reinterpret_cast<float4*>(out) + i1, o1);

    float w1c = g_w1[bc0 + 2], w1d = g_w1[bc0 + 3];
    float c0_ = g_w2[gbase + 0 * C_ + cb + 2], d0 = g_w2[gbase + 0 * C_ + cb + 3];
    float c1_ = g_w2[gbase + 1 * C_ + cb + 2], d1 = g_w2[gbase + 1 * C_ + cb + 3];
    float c2_ = g_w2[gbase + 2 * C_ + cb + 2], d2 = g_w2[gbase + 2 * C_ + cb + 3];
    float c3_ = g_w2[gbase + 3 * C_ + cb + 2], d3 = g_w2[gbase + 3 * C_ + cb + 3];

    float4 o2;
    o2.x = fmaf(yc.x, w1c, fmaf(c0_, r0.x, fmaf(c1_, r1.x, fmaf(c2_, r2.x, c3_ * r3.x))));
    o2.y = fmaf(yc.y, w1c, fmaf(c0_, r0.y, fmaf(c1_, r1.y, fmaf(c2_, r2.y, c3_ * r3.y))));
    o2.z = fmaf(yc.z, w1c, fmaf(c0_, r0.z, fmaf(c1_, r1.z, fmaf(c2_, r2.z, c3_ * r3.z))));
    o2.w = fmaf(yc.w, w1c, fmaf(c0_, r0.w, fmaf(c1_, r1.w, fmaf(c2_, r2.w, c3_ * r3.w))));
    __stcs(reinterpret_cast<float4*>(out) + i2, o2);

    float4 o3;
    o3.x = fmaf(yd.x, w1d, fmaf(d0, s0.x, fmaf(d1, s1.x, fmaf(d2, s2.x, d3 * s3.x))));
    o3.y = fmaf(yd.y, w1d, fmaf(d0, s0.y, fmaf(d1, s1.y, fmaf(d2, s2.y, d3 * s3.y))));
    o3.z = fmaf(yd.z, w1d, fmaf(d0, s0.z, fmaf(d1, s1.z, fmaf(d2, s2.z, d3 * s3.z))));
    o3.w = fmaf(yd.w, w1d, fmaf(d0, s0.w, fmaf(d1, s1.w, fmaf(d2, s2.w, d3 * s3.w))));
    __stcs(reinterpret_cast<float4*>(out) + i3, o3);
}

extern "C" void kernel_launch(void* const* d_in, const int* in_sizes, int n_in,
                              void* d_out, int out_size) {
    const float* y       = (const float*)d_in[0];
    const float* x0      = (const float*)d_in[1];
    const float* x1      = (const float*)d_in[2];
    const float* x2      = (const float*)d_in[3];
    const float* x3      = (const float*)d_in[4];
    const float* conv1_w = (const float*)d_in[5];
    const float* bn_g    = (const float*)d_in[6];
    const float* bn_b    = (const float*)d_in[7];
    const float* bn_m    = (const float*)d_in[8];
    const float* bn_v    = (const float*)d_in[9];
    const float* conv2_w = (const float*)d_in[10];
    const float* conv2_b = (const float*)d_in[11];
    float* out = (float*)d_out;

    k_means<<<5120, 256>>>(y, x0, x1, x2, x3);

    cudaLaunchAttribute attr[1];
    attr[0].id = cudaLaunchAttributeProgrammaticStreamSerialization;
    attr[0].val.programmaticStreamSerializationAllowed = 1;

    {   cudaLaunchConfig_t cfg = {};
        cfg.gridDim = dim3(32, 1, 1);
        cfg.blockDim = dim3(256, 1, 1);
        cfg.stream = 0; cfg.attrs = attr; cfg.numAttrs = 1;
        cudaLaunchKernelEx(&cfg, k_gate1, conv1_w, bn_g, bn_b, bn_m, bn_v);
    }
    {   cudaLaunchConfig_t cfg = {};
        cfg.gridDim = dim3(32, 1, 1);
        cfg.blockDim = dim3(256, 1, 1);
        cfg.stream = 0; cfg.attrs = attr; cfg.numAttrs = 1;
        cudaLaunchKernelEx(&cfg, k_gate2, conv2_w, conv2_b);
    }
    {   // 2097152 float4 / (256 threads * 4 sweeps) -> 2048 blocks
        cudaLaunchConfig_t cfg = {};
        cfg.gridDim = dim3(2048, 1, 1);
        cfg.blockDim = dim3(256, 1, 1);
        cfg.stream = 0; cfg.attrs = attr; cfg.numAttrs = 1;
        cudaLaunchKernelEx(&cfg, k_apply, y, x0, x1, x2, x3, out);
    }
}

// round 17
// speedup vs baseline: 1.0559x; 1.0559x over previous
#include <cuda_runtime.h>
#include <math.h>

// Scratch (no cudaMalloc allowed)
__device__ float g_feats[32 * 1280];   // [B, (K+1)*C] pooled means
__device__ float g_h[32 * 32];         // [MID][B] hidden after BN+ReLU (transposed)
__device__ float g_w1[32 * 256];       // [B, C] sigmoid self-gate
__device__ float g_w2[32 * 4 * 256];   // [B, K, C] softmax branch gates

#define B_ 32
#define C_ 256
#define K_ 4
#define HW_ 1024
#define MID_ 32
#define FEAT_ 1280   // (K+1)*C

// ---------------- Kernel 1: global average pool (proven best config) ----------------
// One warp per (b, slot, c) row of 1024 contiguous floats. 40960 warps total.
__global__ void k_means(const float* __restrict__ y,
                        const float* __restrict__ x0,
                        const float* __restrict__ x1,
                        const float* __restrict__ x2,
                        const float* __restrict__ x3) {
    int warp = (blockIdx.x * blockDim.x + threadIdx.x) >> 5;
    int lane = threadIdx.x & 31;
    int b = warp / FEAT_;
    int j = warp - b * FEAT_;       // slot*256 + c
    int slot = j >> 8;
    int c = j & 255;
    const float* base;
    switch (slot) {
        case 0: base = y;  break;
        case 1: base = x0; break;
        case 2: base = x1; break;
        case 3: base = x2; break;
        default: base = x3; break;
    }
    const float4* p = reinterpret_cast<const float4*>(base + (size_t)(b * C_ + c) * HW_);
    float s = 0.f;
#pragma unroll
    for (int i = 0; i < 8; i++) {
        float4 v = p[lane + i * 32];
        s += (v.x + v.y) + (v.z + v.w);
    }
#pragma unroll
    for (int o = 16; o; o >>= 1) s += __shfl_xor_sync(0xffffffffu, s, o);
    if (lane == 0) g_feats[warp] = s * (1.0f / 1024.0f);
}

// ---------------- Kernel 2a: GEMM1 + BN + ReLU, weight-coalesced ----------------
// One block per mid channel (32 blocks). Weight row loaded to smem BEFORE the
// grid dependency sync -> weight DRAM latency overlaps k_means' tail.
__global__ void k_gate1(const float* __restrict__ conv1_w,   // [32,1280]
                        const float* __restrict__ bn_gamma,
                        const float* __restrict__ bn_beta,
                        const float* __restrict__ bn_mean,
                        const float* __restrict__ bn_var) {
    cudaTriggerProgrammaticLaunchCompletion();   // let k_gate2 launch now

    int m = blockIdx.x;
    int t = threadIdx.x;
    __shared__ float sw[FEAT_];

    // Gate-independent: weight row + BN scalars (overlap with k_means)
    for (int i = t; i < FEAT_; i += 256) sw[i] = conv1_w[m * FEAT_ + i];
    float mean = bn_mean[m];
    float scale = bn_gamma[m] * rsqrtf(bn_var[m] + 1e-5f);
    float beta = bn_beta[m];

    cudaGridDependencySynchronize();             // wait for g_feats
    __syncthreads();

    int w = t >> 5, lane = t & 31;
    // Each of 8 warps handles 4 batches
#pragma unroll
    for (int bb = 0; bb < 4; bb++) {
        int b = w * 4 + bb;
        const float* f = g_feats + b * FEAT_;
        float s = 0.f;
#pragma unroll
        for (int k = 0; k < FEAT_ / 32; k++)
            s = fmaf(f[lane + k * 32], sw[lane + k * 32], s);
#pragma unroll
        for (int o = 16; o; o >>= 1) s += __shfl_xor_sync(0xffffffffu, s, o);
        if (lane == 0)
            g_h[m * B_ + b] = fmaxf(fmaf(s - mean, scale, beta), 0.f);
    }
}

// ---------------- Kernel 2b: GEMM2 + activations, weight-coalesced ----------------
// One block per group of 8 channels (32 blocks). conv2_w slice + biases loaded
// BEFORE the sync; h loaded after. Thread (b, c_local) computes all 5 slots.
__global__ void k_gate2(const float* __restrict__ conv2_w,   // [1280,32]
                        const float* __restrict__ conv2_b) { // [1280]
    cudaTriggerProgrammaticLaunchCompletion();   // let k_apply launch now

    int cg = blockIdx.x;        // channel group: channels [cg*8, cg*8+8)
    int t = threadIdx.x;        // 256
    int c_local = t & 7;
    int b = t >> 3;

    __shared__ float sh2[5 * 8 * 33];            // [slot][c_local][mid], padded
    __shared__ float shh[MID_ * B_];             // [mid][b]

    // Gate-independent: conv2_w slice (5 x 256 contiguous floats) + biases
#pragma unroll
    for (int slot = 0; slot < 5; slot++) {
        int row = t >> 5, mid = t & 31;          // 8 rows x 32 mids = 256
        sh2[(slot * 8 + row) * 33 + mid] = conv2_w[(slot * 256 + cg * 8) * 32 + t];
    }
    float bias[5];
#pragma unroll
    for (int slot = 0; slot < 5; slot++)
        bias[slot] = conv2_b[slot * 256 + cg * 8 + c_local];

    cudaGridDependencySynchronize();             // wait for g_h
    for (int i = t; i < MID_ * B_; i += 256) shh[i] = g_h[i];
    __syncthreads();

    int c = cg * 8 + c_local;
    float v[5];
#pragma unroll
    for (int slot = 0; slot < 5; slot++) {
        float s = bias[slot];
        const float* wp = &sh2[(slot * 8 + c_local) * 33];
#pragma unroll
        for (int mid = 0; mid < MID_; mid++)
            s = fmaf(shh[mid * B_ + b], wp[mid], s);
        v[slot] = s;
    }

    g_w1[b * C_ + c] = 1.0f / (1.0f + expf(-v[0]));
    float mx = fmaxf(fmaxf(v[1], v[2]), fmaxf(v[3], v[4]));
    float e1 = expf(v[1] - mx), e2 = expf(v[2] - mx);
    float e3 = expf(v[3] - mx), e4 = expf(v[4] - mx);
    float inv = 1.0f / (e1 + e2 + e3 + e4);
    int gb = b * K_ * C_ + c;
    g_w2[gb + 0 * C_] = e1 * inv;
    g_w2[gb + 1 * C_] = e2 * inv;
    g_w2[gb + 2 * C_] = e3 * inv;
    g_w2[gb + 3 * C_] = e4 * inv;
}

// ---------------- Kernel 3: apply gates (2 sweeps/thread, reversed, PDL) -----------
__global__ void k_apply(const float* __restrict__ y,
                        const float* __restrict__ x0,
                        const float* __restrict__ x1,
                        const float* __restrict__ x2,
                        const float* __restrict__ x3,
                        float* __restrict__ out) {
    int blk = gridDim.x - 1 - blockIdx.x;            // reversed
    int t = threadIdx.x;
    int i0 = blk * 512 + t;
    int i1 = i0 + 256;

    const float4* Y  = reinterpret_cast<const float4*>(y);
    const float4* X0 = reinterpret_cast<const float4*>(x0);
    const float4* X1 = reinterpret_cast<const float4*>(x1);
    const float4* X2 = reinterpret_cast<const float4*>(x2);
    const float4* X3 = reinterpret_cast<const float4*>(x3);

    // Gate-independent loads first (overlap with gate kernels via PDL)
    float4 ya = Y[i0],  yb = Y[i1];
    float4 p0 = X0[i0], q0 = X0[i1];
    float4 p1 = X1[i0], q1 = X1[i1];
    float4 p2 = X2[i0], q2 = X2[i1];
    float4 p3 = X3[i0], q3 = X3[i1];

    cudaGridDependencySynchronize();

    int bc0 = blk * 2;
    int bc1 = bc0 + 1;
    int b = bc0 >> 8;
    int c0 = bc0 & 255, c1 = bc1 & 255;
    float w1a = g_w1[bc0],               w1b = g_w1[bc1];
    int ga = b * K_ * C_ + c0,           gb = b * K_ * C_ + c1;
    float a0 = g_w2[ga + 0 * C_], b0 = g_w2[gb + 0 * C_];
    float a1 = g_w2[ga + 1 * C_], b1 = g_w2[gb + 1 * C_];
    float a2 = g_w2[ga + 2 * C_], b2 = g_w2[gb + 2 * C_];
    float a3 = g_w2[ga + 3 * C_], b3 = g_w2[gb + 3 * C_];

    float4 r;
    r.x = fmaf(ya.x, w1a, fmaf(a0, p0.x, fmaf(a1, p1.x, fmaf(a2, p2.x, a3 * p3.x))));
    r.y = fmaf(ya.y, w1a, fmaf(a0, p0.y, fmaf(a1, p1.y, fmaf(a2, p2.y, a3 * p3.y))));
    r.z = fmaf(ya.z, w1a, fmaf(a0, p0.z, fmaf(a1, p1.z, fmaf(a2, p2.z, a3 * p3.z))));
    r.w = fmaf(ya.w, w1a, fmaf(a0, p0.w, fmaf(a1, p1.w, fmaf(a2, p2.w, a3 * p3.w))));
    __stcs(reinterpret_cast<float4*>(out) + i0, r);

    float4 s;
    s.x = fmaf(yb.x, w1b, fmaf(b0, q0.x, fmaf(b1, q1.x, fmaf(b2, q2.x, b3 * q3.x))));
    s.y = fmaf(yb.y, w1b, fmaf(b0, q0.y, fmaf(b1, q1.y, fmaf(b2, q2.y, b3 * q3.y))));
    s.z = fmaf(yb.z, w1b, fmaf(b0, q0.z, fmaf(b1, q1.z, fmaf(b2, q2.z, b3 * q3.z))));
    s.w = fmaf(yb.w, w1b, fmaf(b0, q0.w, fmaf(b1, q1.w, fmaf(b2, q2.w, b3 * q3.w))));
    __stcs(reinterpret_cast<float4*>(out) + i1, s);
}

extern "C" void kernel_launch(void* const* d_in, const int* in_sizes, int n_in,
                              void* d_out, int out_size) {
    const float* y       = (const float*)d_in[0];
    const float* x0      = (const float*)d_in[1];
    const float* x1      = (const float*)d_in[2];
    const float* x2      = (const float*)d_in[3];
    const float* x3      = (const float*)d_in[4];
    const float* conv1_w = (const float*)d_in[5];
    const float* bn_g    = (const float*)d_in[6];
    const float* bn_b    = (const float*)d_in[7];
    const float* bn_m    = (const float*)d_in[8];
    const float* bn_v    = (const float*)d_in[9];
    const float* conv2_w = (const float*)d_in[10];
    const float* conv2_b = (const float*)d_in[11];
    float* out = (float*)d_out;

    k_means<<<5120, 256>>>(y, x0, x1, x2, x3);

    cudaLaunchAttribute attr[1];
    attr[0].id = cudaLaunchAttributeProgrammaticStreamSerialization;
    attr[0].val.programmaticStreamSerializationAllowed = 1;

    {   // GEMM1+BN+ReLU
        cudaLaunchConfig_t cfg = {};
        cfg.gridDim = dim3(32, 1, 1);
        cfg.blockDim = dim3(256, 1, 1);
        cfg.stream = 0;
        cfg.attrs = attr;
        cfg.numAttrs = 1;
        cudaLaunchKernelEx(&cfg, k_gate1, conv1_w, bn_g, bn_b, bn_m, bn_v);
    }
    {   // GEMM2+activations
        cudaLaunchConfig_t cfg = {};
        cfg.gridDim = dim3(32, 1, 1);
        cfg.blockDim = dim3(256, 1, 1);
        cfg.stream = 0;
        cfg.attrs = attr;
        cfg.numAttrs = 1;
        cudaLaunchKernelEx(&cfg, k_gate2, conv2_w, conv2_b);
    }
    {   // apply
        cudaLaunchConfig_t cfg = {};
        cfg.gridDim = dim3(4096, 1, 1);
        cfg.blockDim = dim3(256, 1, 1);
        cfg.stream = 0;
        cfg.attrs = attr;
        cfg.numAttrs = 1;
        cudaLaunchKernelEx(&cfg, k_apply, y, x0, x1, x2, x3, out);
    }
}